// round 8
// baseline (speedup 1.0000x reference)
#include <cuda_runtime.h>
#include <cuda_fp16.h>

// x[32, 336, 32, 32] fp32, moving-avg k=25 (replicate pad), seasonal period 24
#define BB     32
#define CC     336
#define KS     25
#define PE     24
#define NG     (CC / PE)          // 14
#define HWW    1024
#define HW4    (HWW / 4)          // 256 float4 per (b,c) plane
#define NCOL4  (BB * HW4)         // 8192 float4-columns
#define NELEM  ((size_t)BB * CC * HWW)

#define COLS4   8                 // float4 columns per block
#define COLS4P  (COLS4 + 1)       // padded: shifts g-subgroups across bank halves
#define NTHREAD (COLS4 * NG)      // 112

__device__ __forceinline__ float4 f4_add(float4 a, float4 b) {
    return make_float4(a.x + b.x, a.y + b.y, a.z + b.z, a.w + b.w);
}
__device__ __forceinline__ float4 f4_sub(float4 a, float4 b) {
    return make_float4(a.x - b.x, a.y - b.y, a.z - b.z, a.w - b.w);
}
__device__ __forceinline__ float4 f4_scale(float4 a, float s) {
    return make_float4(a.x * s, a.y * s, a.z * s, a.w * s);
}

__global__ __launch_bounds__(NTHREAD, 8)   // 71-reg cap -> 8 blocks/SM, whole grid resident
void decomp_kernel(const float4* __restrict__ x,
                   float4* __restrict__ To,
                   float4* __restrict__ So,
                   float4* __restrict__ Ro)
{
    // detrended values in fp16: [NG][PE][COLS4+1][2] half2  (~24 KB)
    __shared__ __half2 xd_s[NG][PE][COLS4P][2];
    __shared__ float4  acc[PE][COLS4];      // seasonal means, fp32 (3 KB)

    const int tx = threadIdx.x;             // [0,8) float4 column lane
    const int g  = threadIdx.y;             // [0,14) channel group
    const int col4 = blockIdx.x * COLS4 + tx;
    const int b   = col4 >> 8;              // col4 / 256
    const int hw4 = col4 & (HW4 - 1);

    const size_t base = (size_t)b * CC * HW4 + hw4;
    const float4* __restrict__ xp = x + base;

    const float inv_k = 1.0f / (float)KS;
    const float inv_g = 1.0f / (float)NG;
    const int   c0    = g * PE;

    // initial window sum at c = c0: sum_{j=-12..12} x[clamp(c0+j)]
    float4 wsum = make_float4(0.f, 0.f, 0.f, 0.f);
    #pragma unroll
    for (int j = -12; j <= 12; j++) {
        int cc = c0 + j;
        cc = cc < 0 ? 0 : (cc > CC - 1 ? CC - 1 : cc);
        wsum = f4_add(wsum, xp[(size_t)cc * HW4]);
    }

    // ---- Pass A: trend (write To), stash detrended (fp16) in smem ----
    #pragma unroll
    for (int p = 0; p < PE; p++) {
        const int c = c0 + p;
        float4 T  = f4_scale(wsum, inv_k);
        float4 xc = xp[(size_t)c * HW4];
        __stcs(&To[base + (size_t)c * HW4], T);   // evict-first: never re-read
        float4 xd = f4_sub(xc, T);
        xd_s[g][p][tx][0] = __floats2half2_rn(xd.x, xd.y);
        xd_s[g][p][tx][1] = __floats2half2_rn(xd.z, xd.w);
        int cin  = c + 13; if (cin  > CC - 1) cin  = CC - 1;
        int cout = c - 12; if (cout < 0)      cout = 0;
        wsum = f4_add(wsum, f4_sub(xp[(size_t)cin * HW4], xp[(size_t)cout * HW4]));
    }

    __syncthreads();

    // ---- Cross-group reduction (fp32 accumulate): each thread owns (p,t) pairs ----
    {
        const int lin = threadIdx.y * COLS4 + threadIdx.x;
        #pragma unroll
        for (int idx = lin; idx < PE * COLS4; idx += NTHREAD) {
            const int p = idx >> 3;            // / COLS4
            const int t = idx & (COLS4 - 1);
            float2 s0 = make_float2(0.f, 0.f);
            float2 s1 = make_float2(0.f, 0.f);
            #pragma unroll
            for (int gg = 0; gg < NG; gg++) {
                float2 a0 = __half22float2(xd_s[gg][p][t][0]);
                float2 a1 = __half22float2(xd_s[gg][p][t][1]);
                s0.x += a0.x; s0.y += a0.y;
                s1.x += a1.x; s1.y += a1.y;
            }
            acc[p][t] = make_float4(s0.x * inv_g, s0.y * inv_g,
                                    s1.x * inv_g, s1.y * inv_g);
        }
    }

    __syncthreads();

    // ---- Pass B: emit seasonal + residual from smem (no global re-reads) ----
    #pragma unroll
    for (int p = 0; p < PE; p++) {
        const int c = c0 + p;
        float4 S  = acc[p][tx];
        float2 d0 = __half22float2(xd_s[g][p][tx][0]);
        float2 d1 = __half22float2(xd_s[g][p][tx][1]);
        float4 R  = make_float4(d0.x - S.x, d0.y - S.y, d1.x - S.z, d1.y - S.w);
        __stcs(&So[base + (size_t)c * HW4], S);
        __stcs(&Ro[base + (size_t)c * HW4], R);
    }
}

extern "C" void kernel_launch(void* const* d_in, const int* in_sizes, int n_in,
                              void* d_out, int out_size)
{
    const float4* x = (const float4*)d_in[0];
    float* out = (float*)d_out;
    float4* To = (float4*)out;
    float4* So = (float4*)(out + NELEM);
    float4* Ro = (float4*)(out + 2 * NELEM);
    dim3 blk(COLS4, NG);
    decomp_kernel<<<NCOL4 / COLS4, blk>>>(x, To, So, Ro);
}

// round 11
// speedup vs baseline: 1.0016x; 1.0016x over previous
#include <cuda_runtime.h>

// x[32, 336, 32, 32] fp32, moving-avg k=25 (replicate pad), seasonal period 24
#define BB     32
#define CC     336
#define KS     25
#define PE     24
#define NG     (CC / PE)          // 14
#define HWW    1024
#define HW4    (HWW / 4)          // 256 float4 per (b,c) plane
#define NCOL4  (BB * HW4)         // 8192 float4-columns
#define NELEM  ((size_t)BB * CC * HWW)

#define COLS4   8                 // float4 columns per block
#define NTHREAD (COLS4 * NG)      // 112

__device__ __forceinline__ float4 f4_add(float4 a, float4 b) {
    return make_float4(a.x + b.x, a.y + b.y, a.z + b.z, a.w + b.w);
}
__device__ __forceinline__ float4 f4_sub(float4 a, float4 b) {
    return make_float4(a.x - b.x, a.y - b.y, a.z - b.z, a.w - b.w);
}
__device__ __forceinline__ float4 f4_scale(float4 a, float s) {
    return make_float4(a.x * s, a.y * s, a.z * s, a.w * s);
}

__global__ __launch_bounds__(NTHREAD, 4)
void decomp_kernel(const float4* __restrict__ x,
                   float4* __restrict__ To,
                   float4* __restrict__ So,
                   float4* __restrict__ Ro)
{
    __shared__ float4 xs[CC][COLS4];     // staged input column-set (42 KB)
    __shared__ float4 acc[PE][COLS4];    // seasonal sums, fp32 (1.5 KB)

    const int tx = threadIdx.x;          // [0,8) float4 column lane
    const int g  = threadIdx.y;          // [0,14) channel group
    const int tid = g * COLS4 + tx;
    const int col4 = blockIdx.x * COLS4 + tx;
    const int b   = col4 >> 8;
    const int hw4 = col4 & (HW4 - 1);

    const size_t base = (size_t)b * CC * HW4 + hw4;
    const float4* __restrict__ xp = x + base;

    const float inv_k = 1.0f / (float)KS;
    const float inv_g = 1.0f / (float)NG;
    const int   c0    = g * PE;

    // zero the FULL reduction buffer (PE*COLS4 = 192 entries > NTHREAD)
    #pragma unroll
    for (int i = tid; i < PE * COLS4; i += NTHREAD) {
        ((float4*)acc)[i] = make_float4(0.f, 0.f, 0.f, 0.f);
    }

    // ---- Stage: cooperative load of all 336 channels (x read ONCE from global) ----
    #pragma unroll
    for (int j = 0; j < PE; j++) {
        const int c = g + j * NG;        // g + 14*j covers [0, 336)
        xs[c][tx] = xp[(size_t)c * HW4];
    }
    __syncthreads();

    // ---- Pass A: sliding trend from smem, write To, reduce xd into acc ----
    float4 wsum = make_float4(0.f, 0.f, 0.f, 0.f);
    #pragma unroll
    for (int j = -12; j <= 12; j++) {
        int cc = c0 + j;
        cc = cc < 0 ? 0 : (cc > CC - 1 ? CC - 1 : cc);
        wsum = f4_add(wsum, xs[cc][tx]);
    }
    const float4 wsum0 = wsum;

    // warps 0-2 are full (4 groups each); warp 3 has only 16 lanes (groups 12,13)
    const bool full_warp = ((tid >> 5) < 3);
    const unsigned wmask = full_warp ? 0xFFFFFFFFu : 0x0000FFFFu;
    const bool leader    = full_warp ? ((g & 3) == 0) : (g == 12);

    #pragma unroll
    for (int p = 0; p < PE; p++) {
        const int c = c0 + p;
        float4 T  = f4_scale(wsum, inv_k);
        float4 xc = xs[c][tx];
        __stcs(&To[base + (size_t)c * HW4], T);
        float4 xd = f4_sub(xc, T);

        // shfl-reduce xd over the groups sharing this warp
        xd.x += __shfl_xor_sync(wmask, xd.x, 8);
        xd.y += __shfl_xor_sync(wmask, xd.y, 8);
        xd.z += __shfl_xor_sync(wmask, xd.z, 8);
        xd.w += __shfl_xor_sync(wmask, xd.w, 8);
        if (full_warp) {
            xd.x += __shfl_xor_sync(wmask, xd.x, 16);
            xd.y += __shfl_xor_sync(wmask, xd.y, 16);
            xd.z += __shfl_xor_sync(wmask, xd.z, 16);
            xd.w += __shfl_xor_sync(wmask, xd.w, 16);
        }
        if (leader) {
            atomicAdd(&acc[p][tx].x, xd.x);
            atomicAdd(&acc[p][tx].y, xd.y);
            atomicAdd(&acc[p][tx].z, xd.z);
            atomicAdd(&acc[p][tx].w, xd.w);
        }

        int cin  = c + 13; if (cin  > CC - 1) cin  = CC - 1;
        int cout = c - 12; if (cout < 0)      cout = 0;
        wsum = f4_add(wsum, f4_sub(xs[cin][tx], xs[cout][tx]));
    }

    __syncthreads();

    // ---- Pass B: recompute identical trend from smem, emit S and R ----
    wsum = wsum0;
    #pragma unroll
    for (int p = 0; p < PE; p++) {
        const int c = c0 + p;
        float4 T  = f4_scale(wsum, inv_k);
        float4 xc = xs[c][tx];
        float4 S  = f4_scale(acc[p][tx], inv_g);
        float4 R  = f4_sub(f4_sub(xc, T), S);
        __stcs(&So[base + (size_t)c * HW4], S);
        __stcs(&Ro[base + (size_t)c * HW4], R);
        int cin  = c + 13; if (cin  > CC - 1) cin  = CC - 1;
        int cout = c - 12; if (cout < 0)      cout = 0;
        wsum = f4_add(wsum, f4_sub(xs[cin][tx], xs[cout][tx]));
    }
}

extern "C" void kernel_launch(void* const* d_in, const int* in_sizes, int n_in,
                              void* d_out, int out_size)
{
    const float4* x = (const float4*)d_in[0];
    float* out = (float*)d_out;
    float4* To = (float4*)out;
    float4* So = (float4*)(out + NELEM);
    float4* Ro = (float4*)(out + 2 * NELEM);
    dim3 blk(COLS4, NG);
    decomp_kernel<<<NCOL4 / COLS4, blk>>>(x, To, So, Ro);
}

// round 12
// speedup vs baseline: 1.1630x; 1.1612x over previous
#include <cuda_runtime.h>

// x[32, 336, 32, 32] fp32, moving-avg k=25 (replicate pad), seasonal period 24
#define BB     32
#define CC     336
#define KS     25
#define PE     24
#define NG     (CC / PE)          // 14
#define HWW    1024
#define HW4    (HWW / 4)          // 256 float4 per (b,c) plane
#define NCOL4  (BB * HW4)         // 8192 float4-columns
#define NELEM  ((size_t)BB * CC * HWW)

#define COLS4   8                 // float4 columns per block
#define NTHREAD (COLS4 * NG)      // 112

__device__ __forceinline__ float4 f4_add(float4 a, float4 b) {
    return make_float4(a.x + b.x, a.y + b.y, a.z + b.z, a.w + b.w);
}
__device__ __forceinline__ float4 f4_sub(float4 a, float4 b) {
    return make_float4(a.x - b.x, a.y - b.y, a.z - b.z, a.w - b.w);
}
__device__ __forceinline__ float4 f4_scale(float4 a, float s) {
    return make_float4(a.x * s, a.y * s, a.z * s, a.w * s);
}

__global__ __launch_bounds__(NTHREAD, 4)
void decomp_kernel(const float4* __restrict__ x,
                   float4* __restrict__ To,
                   float4* __restrict__ So,
                   float4* __restrict__ Ro)
{
    __shared__ float4 xd_s[NG][PE][COLS4];  // detrended values (43 KB)
    __shared__ float4 acc[PE][COLS4];       // seasonal means (3 KB)

    const int tx = threadIdx.x;             // [0,8) float4 column lane
    const int g  = threadIdx.y;             // [0,14) channel group
    const int col4 = blockIdx.x * COLS4 + tx;
    const int b   = col4 >> 8;
    const int hw4 = col4 & (HW4 - 1);

    const size_t base = (size_t)b * CC * HW4 + hw4;
    const float4* __restrict__ xp = x + base;

    const float inv_k = 1.0f / (float)KS;
    const float inv_g = 1.0f / (float)NG;
    const int   c0    = g * PE;

    // ---- Register ring-buffer: W[j] = x[clamp(c0-12+j)], j=0..24 ----
    // All 25 loads independent -> deep MLP batch; each distinct value loaded ONCE.
    float4 W[KS];
    #pragma unroll
    for (int j = 0; j < KS; j++) {
        int cc = c0 - 12 + j;
        cc = cc < 0 ? 0 : (cc > CC - 1 ? CC - 1 : cc);
        W[j] = xp[(size_t)cc * HW4];
    }
    float4 wsum = make_float4(0.f, 0.f, 0.f, 0.f);
    #pragma unroll
    for (int j = 0; j < KS; j++) wsum = f4_add(wsum, W[j]);

    // ---- Pass A: trend (write To), stash detrended in smem; 1 load/step ----
    #pragma unroll
    for (int p = 0; p < PE; p++) {
        const int c = c0 + p;
        float4 T  = f4_scale(wsum, inv_k);
        float4 xc = W[(12 + p) % KS];       // static index under full unroll
        __stcs(&To[base + (size_t)c * HW4], T);
        xd_s[g][p][tx] = f4_sub(xc, T);

        int cin = c + 13; if (cin > CC - 1) cin = CC - 1;
        float4 vin  = xp[(size_t)cin * HW4];   // the ONLY global load per step
        float4 vout = W[p % KS];               // x[c-12] from the ring (p<25 -> ==W[p])
        wsum = f4_add(wsum, f4_sub(vin, vout));
        W[p % KS] = vin;                        // recycle oldest slot
    }

    __syncthreads();

    // ---- Cross-group reduction (no atomics): each thread owns (p, t) pairs ----
    {
        const int tid = g * COLS4 + tx;
        #pragma unroll
        for (int idx = tid; idx < PE * COLS4; idx += NTHREAD) {
            const int p = idx >> 3;             // / COLS4
            const int t = idx & (COLS4 - 1);
            float4 s = make_float4(0.f, 0.f, 0.f, 0.f);
            #pragma unroll
            for (int gg = 0; gg < NG; gg++) s = f4_add(s, xd_s[gg][p][t]);
            acc[p][t] = f4_scale(s, inv_g);
        }
    }

    __syncthreads();

    // ---- Pass B: emit seasonal + residual from smem (no global re-reads) ----
    #pragma unroll
    for (int p = 0; p < PE; p++) {
        const int c = c0 + p;
        float4 S  = acc[p][tx];
        float4 xd = xd_s[g][p][tx];
        __stcs(&So[base + (size_t)c * HW4], S);
        __stcs(&Ro[base + (size_t)c * HW4], f4_sub(xd, S));
    }
}

extern "C" void kernel_launch(void* const* d_in, const int* in_sizes, int n_in,
                              void* d_out, int out_size)
{
    const float4* x = (const float4*)d_in[0];
    float* out = (float*)d_out;
    float4* To = (float4*)out;
    float4* So = (float4*)(out + NELEM);
    float4* Ro = (float4*)(out + 2 * NELEM);
    dim3 blk(COLS4, NG);
    decomp_kernel<<<NCOL4 / COLS4, blk>>>(x, To, So, Ro);
}

// round 13
// speedup vs baseline: 1.2738x; 1.0952x over previous
#include <cuda_runtime.h>

// x[32, 336, 32, 32] fp32, moving-avg k=25 (replicate pad), seasonal period 24
#define BB     32
#define CC     336
#define KS     25
#define PE     24
#define NG     (CC / PE)          // 14
#define HWW    1024
#define HW4    (HWW / 4)          // 256 float4 per (b,c) plane
#define NCOL4  (BB * HW4)         // 8192 float4-columns
#define NELEM  ((size_t)BB * CC * HWW)

#define COLS4   8                 // float4 columns per block
#define NTHREAD (COLS4 * NG)      // 112

__device__ __forceinline__ float4 f4_add(float4 a, float4 b) {
    return make_float4(a.x + b.x, a.y + b.y, a.z + b.z, a.w + b.w);
}
__device__ __forceinline__ float4 f4_sub(float4 a, float4 b) {
    return make_float4(a.x - b.x, a.y - b.y, a.z - b.z, a.w - b.w);
}
__device__ __forceinline__ float4 f4_scale(float4 a, float s) {
    return make_float4(a.x * s, a.y * s, a.z * s, a.w * s);
}

__global__ __launch_bounds__(NTHREAD, 5)   // 5 blocks/SM: 117-reg cap, 222.7 KB smem/SM
void decomp_kernel(const float4* __restrict__ x,
                   float4* __restrict__ To,
                   float4* __restrict__ So,
                   float4* __restrict__ Ro)
{
    __shared__ float4 xd_s[NG][PE][COLS4];  // detrended (42 KB)
    __shared__ float4 acc[PE][COLS4];       // seasonal means (1.5 KB)

    const int tx = threadIdx.x;             // [0,8) float4 column lane
    const int g  = threadIdx.y;             // [0,14) channel group
    const int col4 = blockIdx.x * COLS4 + tx;
    const int b   = col4 >> 8;
    const int hw4 = col4 & (HW4 - 1);

    const size_t base = (size_t)b * CC * HW4 + hw4;
    const float4* __restrict__ xp = x + base;

    const float inv_k = 1.0f / (float)KS;
    const float inv_g = 1.0f / (float)NG;
    const int   c0    = g * PE;

    // initial window sum at c = c0: sum_{j=-12..12} x[clamp(c0+j)]
    float4 wsum = make_float4(0.f, 0.f, 0.f, 0.f);
    #pragma unroll
    for (int j = -12; j <= 12; j++) {
        int cc = c0 + j;
        cc = cc < 0 ? 0 : (cc > CC - 1 ? CC - 1 : cc);
        wsum = f4_add(wsum, xp[(size_t)cc * HW4]);
    }

    // ---- Pass A: trend (write To), stash detrended in smem ----
    #pragma unroll
    for (int p = 0; p < PE; p++) {
        const int c = c0 + p;
        float4 T  = f4_scale(wsum, inv_k);
        float4 xc = xp[(size_t)c * HW4];
        __stcs(&To[base + (size_t)c * HW4], T);   // evict-first: never re-read
        xd_s[g][p][tx] = f4_sub(xc, T);
        int cin  = c + 13; if (cin  > CC - 1) cin  = CC - 1;
        int cout = c - 12; if (cout < 0)      cout = 0;
        wsum = f4_add(wsum, f4_sub(xp[(size_t)cin * HW4], xp[(size_t)cout * HW4]));
    }

    __syncthreads();

    // ---- Cross-group reduction: each thread owns (p, t) pairs ----
    {
        const int tid = g * COLS4 + tx;
        #pragma unroll
        for (int idx = tid; idx < PE * COLS4; idx += NTHREAD) {
            const int p = idx >> 3;            // / COLS4
            const int t = idx & (COLS4 - 1);
            float4 s = make_float4(0.f, 0.f, 0.f, 0.f);
            #pragma unroll
            for (int gg = 0; gg < NG; gg++) s = f4_add(s, xd_s[gg][p][t]);
            acc[p][t] = f4_scale(s, inv_g);
        }
    }

    __syncthreads();

    // ---- Pass B: emit seasonal + residual from smem (no global re-reads) ----
    #pragma unroll
    for (int p = 0; p < PE; p++) {
        const int c = c0 + p;
        float4 S  = acc[p][tx];
        float4 xd = xd_s[g][p][tx];
        __stcs(&So[base + (size_t)c * HW4], S);
        __stcs(&Ro[base + (size_t)c * HW4], f4_sub(xd, S));
    }
}

extern "C" void kernel_launch(void* const* d_in, const int* in_sizes, int n_in,
                              void* d_out, int out_size)
{
    const float4* x = (const float4*)d_in[0];
    float* out = (float*)d_out;
    float4* To = (float4*)out;
    float4* So = (float4*)(out + NELEM);
    float4* Ro = (float4*)(out + 2 * NELEM);
    dim3 blk(COLS4, NG);
    decomp_kernel<<<NCOL4 / COLS4, blk>>>(x, To, So, Ro);
}